// round 10
// baseline (speedup 1.0000x reference)
#include <cuda_runtime.h>
#include <cuda_bf16.h>
#include <cuda_fp16.h>

#define NN 50000
#define NE 600000
#define DD 128
#define NT 391            // 128-row tiles covering 50048 rows
#define LDA 136           // padded smem row (bf16 units): 272B, conflict-free ldmatrix
#define NSB 49            // scan blocks: 49 * 1024 >= NN

// ---------------- scratch (device globals; no allocation allowed) ----------------
// counters zero at module load; re-zeroed inside k_finish each call (deterministic)
__device__ int   g_out_cnt[NN];
__device__ int   g_in_cnt[NN];
__device__ int   g_bsum[64];
__device__ int   g_row_off[NN + 1];
__device__ int   g_cursor[NN];
__device__ int   g_csr_src[NE];
__device__ float g_src_norm[NN];
__device__ float g_dst_norm[NN];
// fp16 feature storage (prescaled by src_norm)
__device__ __align__(16) __half g_f16[NN * DD];   // layer-0 input: src_norm * feat
__device__ __align__(16) __half g_p0[NN * DD];    // ping-pong prescaled h
__device__ __align__(16) __half g_p1[NN * DD];
// bf16 split of W (k x n row-major), per layer
__device__ __align__(16) unsigned short g_wh16[4 * DD * DD];
__device__ __align__(16) unsigned short g_wl16[4 * DD * DD];

// ---------------- PTX helpers (base sm_100 compatible only!) ----------------
__device__ __forceinline__ unsigned s2u(const void* p) {
    unsigned r;
    asm("{ .reg .u64 t; cvta.to.shared.u64 t, %1; cvt.u32.u64 %0, t; }" : "=r"(r) : "l"(p));
    return r;
}
#define LDSM_X4(r, a)                                                         \
    asm volatile("ldmatrix.sync.aligned.m8n8.x4.shared.b16 {%0,%1,%2,%3}, [%4];" \
        : "=r"((r)[0]), "=r"((r)[1]), "=r"((r)[2]), "=r"((r)[3]) : "r"(a))
#define LDSM_X4T(r, a)                                                        \
    asm volatile("ldmatrix.sync.aligned.m8n8.x4.trans.shared.b16 {%0,%1,%2,%3}, [%4];" \
        : "=r"((r)[0]), "=r"((r)[1]), "=r"((r)[2]), "=r"((r)[3]) : "r"(a))
#define MMA16816(c, a, b0_, b1_)                                              \
    asm volatile("mma.sync.aligned.m16n8k16.row.col.f32.bf16.bf16.f32 "       \
        "{%0,%1,%2,%3},{%4,%5,%6,%7},{%8,%9},{%0,%1,%2,%3};"                  \
        : "+f"((c)[0]), "+f"((c)[1]), "+f"((c)[2]), "+f"((c)[3])              \
        : "r"((a)[0]), "r"((a)[1]), "r"((a)[2]), "r"((a)[3]), "r"(b0_), "r"(b1_))

// ---------------- CSR build (validated; frozen) ----------------
__global__ void k_count(const int* __restrict__ src, const int* __restrict__ dst) {
    int e = blockIdx.x * blockDim.x + threadIdx.x;
    if (e < NE) {
        atomicAdd(&g_out_cnt[src[e]], 1);
        atomicAdd(&g_in_cnt[dst[e]], 1);
    }
}
__global__ __launch_bounds__(1024) void k_bsum() {
    __shared__ int sd[1024];
    int t = threadIdx.x, b = blockIdx.x;
    int i = b * 1024 + t;
    sd[t] = (i < NN) ? g_in_cnt[i] : 0;
    __syncthreads();
#pragma unroll
    for (int s = 512; s > 0; s >>= 1) {
        if (t < s) sd[t] += sd[t + s];
        __syncthreads();
    }
    if (t == 0) g_bsum[b] = sd[0];
}
__global__ __launch_bounds__(1024) void k_finish() {
    __shared__ int sd[1024];
    __shared__ int sb[NSB + 1];
    int t = threadIdx.x, b = blockIdx.x;
    int i = b * 1024 + t;
    int incnt = (i < NN) ? g_in_cnt[i] : 0;
    sd[t] = incnt;
    __syncthreads();
#pragma unroll
    for (int off = 1; off < 1024; off <<= 1) {
        int v = (t >= off) ? sd[t - off] : 0;
        __syncthreads();
        sd[t] += v;
        __syncthreads();
    }
    int excl = sd[t] - incnt;
    if (t == 0) {
        int run = 0;
        for (int k = 0; k < NSB; k++) { int v = g_bsum[k]; sb[k] = run; run += v; }
        sb[NSB] = run;
    }
    __syncthreads();
    int base = sb[b];
    if (i < NN) {
        int o = base + excl;
        g_row_off[i] = o;
        g_cursor[i]  = o;
        g_src_norm[i] = rsqrtf((float)max(g_out_cnt[i], 1));
        g_dst_norm[i] = rsqrtf((float)max(incnt, 1));
        g_out_cnt[i] = 0;
        g_in_cnt[i]  = 0;
    }
    if (b == 0 && t == 0) g_row_off[NN] = sb[NSB];
}
__global__ void k_fill(const int* __restrict__ src, const int* __restrict__ dst) {
    int e = blockIdx.x * blockDim.x + threadIdx.x;
    if (e < NE) {
        int d = dst[e];
        int p = atomicAdd(&g_cursor[d], 1);
        g_csr_src[p] = src[e];
    }
}
__global__ void k_wconv(const float* __restrict__ W) {
    int idx = blockIdx.x * blockDim.x + threadIdx.x;
    if (idx >= 4 * DD * DD) return;
    float v = W[idx];
    __nv_bfloat16 hi = __float2bfloat16(v);
    float lo = v - __bfloat162float(hi);
    g_wh16[idx] = __bfloat16_as_ushort(hi);
    g_wl16[idx] = __bfloat16_as_ushort(__float2bfloat16(lo));
}
// prescale feat by src_norm, convert to fp16 (4 elems/thread)
__global__ void k_prep(const float* __restrict__ feat) {
    int i4 = blockIdx.x * blockDim.x + threadIdx.x;   // 0 .. NN*DD/4-1
    if (i4 >= NN * DD / 4) return;
    int row = i4 >> 5;                                 // /32 (32 float4 per row)
    float sn = __ldg(&g_src_norm[row]);
    float4 v = __ldg((const float4*)feat + i4);
    __half2 a = __floats2half2_rn(v.x * sn, v.y * sn);
    __half2 b = __floats2half2_rn(v.z * sn, v.w * sn);
    uint2 u; u.x = *(unsigned*)&a; u.y = *(unsigned*)&b;
    *((uint2*)g_f16 + i4) = u;
}

// ---------------- fused aggregate + GEMM -----------------------------------------
// CTA t: nodes [t*128, t*128+128). 1024 threads (32 warps), 1 CTA/SM.
// Phase 1: warp w sums fp16 rows for nodes w*4..w*4+3 (input prescaled by src_norm),
//          scales by dst_norm, splits bf16 hi/lo into ldmatrix-layout smem.
// Phase 2: 32 warps mma, warp tile 32m x 16n, 3-term bf16 split.
// sel: 0 -> g_f16, 1 -> g_p0, 2 -> g_p1. out_sel: 0 -> fp32 ext, 1 -> g_p0, 2 -> g_p1.
#define FSMEM (4 * DD * LDA * 2)

__global__ __launch_bounds__(1024, 1) void k_fused(
        int sel, int layer, const float* __restrict__ bias,
        float* __restrict__ ext_out, int out_sel) {
    extern __shared__ unsigned short smx[];
    unsigned short* sWh = smx;
    unsigned short* sWl = smx + DD * LDA;
    unsigned short* sAh = smx + 2 * DD * LDA;
    unsigned short* sAl = smx + 3 * DD * LDA;

    int tid = threadIdx.x, lane = tid & 31, w = tid >> 5;
    int t = blockIdx.x;
    const uint2* h2 = (const uint2*)(sel == 0 ? g_f16 : (sel == 1 ? g_p0 : g_p1));

    // stage W (1024 threads x 2 uint4 each per array)
    {
        const uint4* w_h = (const uint4*)(g_wh16 + layer * DD * DD);
        const uint4* w_l = (const uint4*)(g_wl16 + layer * DD * DD);
#pragma unroll
        for (int i = 0; i < 2; i++) {
            int li = tid + i * 1024;
            int r = li >> 4, c = li & 15;
            int d = r * LDA + c * 8;
            *(uint4*)&sWh[d] = w_h[li];
            *(uint4*)&sWl[d] = w_l[li];
        }
    }

    // ---------------- phase 1: sum fp16 rows, 4 nodes per warp ----------------
#pragma unroll
    for (int q = 0; q < 4; q++) {
        int r = w * 4 + q;              // local row 0..127
        int gw = t * DD + r;
        float4 acc = make_float4(0.f, 0.f, 0.f, 0.f);
        if (gw < NN) {
            int beg = __ldg(&g_row_off[gw]), end = __ldg(&g_row_off[gw + 1]);
            int j = beg;
            for (; j + 4 <= end; j += 4) {
                int s0 = __ldg(&g_csr_src[j]),     s1 = __ldg(&g_csr_src[j + 1]);
                int s2 = __ldg(&g_csr_src[j + 2]), s3 = __ldg(&g_csr_src[j + 3]);
                uint2 u0 = __ldg(&h2[s0 * 32 + lane]);
                uint2 u1 = __ldg(&h2[s1 * 32 + lane]);
                uint2 u2 = __ldg(&h2[s2 * 32 + lane]);
                uint2 u3 = __ldg(&h2[s3 * 32 + lane]);
                float2 a0 = __half22float2(*(__half2*)&u0.x), b0 = __half22float2(*(__half2*)&u0.y);
                float2 a1 = __half22float2(*(__half2*)&u1.x), b1 = __half22float2(*(__half2*)&u1.y);
                float2 a2 = __half22float2(*(__half2*)&u2.x), b2 = __half22float2(*(__half2*)&u2.y);
                float2 a3 = __half22float2(*(__half2*)&u3.x), b3 = __half22float2(*(__half2*)&u3.y);
                acc.x += a0.x + a1.x + a2.x + a3.x;
                acc.y += a0.y + a1.y + a2.y + a3.y;
                acc.z += b0.x + b1.x + b2.x + b3.x;
                acc.w += b0.y + b1.y + b2.y + b3.y;
            }
            for (; j < end; j++) {
                int s0 = __ldg(&g_csr_src[j]);
                uint2 u0 = __ldg(&h2[s0 * 32 + lane]);
                float2 a0 = __half22float2(*(__half2*)&u0.x), b0 = __half22float2(*(__half2*)&u0.y);
                acc.x += a0.x; acc.y += a0.y; acc.z += b0.x; acc.w += b0.y;
            }
            float dn = __ldg(&g_dst_norm[gw]);
            acc.x *= dn; acc.y *= dn; acc.z *= dn; acc.w *= dn;
        }
        // split to bf16 hi/lo, store to smem in ldmatrix layout
        __nv_bfloat16 hx = __float2bfloat16(acc.x), hy = __float2bfloat16(acc.y);
        __nv_bfloat16 hz = __float2bfloat16(acc.z), hw = __float2bfloat16(acc.w);
        ushort4 vh, vl;
        vh.x = __bfloat16_as_ushort(hx); vh.y = __bfloat16_as_ushort(hy);
        vh.z = __bfloat16_as_ushort(hz); vh.w = __bfloat16_as_ushort(hw);
        vl.x = __bfloat16_as_ushort(__float2bfloat16(acc.x - __bfloat162float(hx)));
        vl.y = __bfloat16_as_ushort(__float2bfloat16(acc.y - __bfloat162float(hy)));
        vl.z = __bfloat16_as_ushort(__float2bfloat16(acc.z - __bfloat162float(hz)));
        vl.w = __bfloat16_as_ushort(__float2bfloat16(acc.w - __bfloat162float(hw)));
        *(ushort4*)&sAh[r * LDA + lane * 4] = vh;
        *(ushort4*)&sAl[r * LDA + lane * 4] = vl;
    }
    __syncthreads();

    // ---------------- phase 2: 3-term mma, warp tile 32m x 16n ----------------
    int mw = w & 3, nw = w >> 2;     // 4 m-groups x 8 n-groups

    float acc2[2][2][4];
#pragma unroll
    for (int mt = 0; mt < 2; mt++)
#pragma unroll
        for (int nt = 0; nt < 2; nt++)
#pragma unroll
            for (int q = 0; q < 4; q++) acc2[mt][nt][q] = 0.f;

    unsigned aH[2], aL[2];
#pragma unroll
    for (int mt = 0; mt < 2; mt++) {
        int r = mw * 32 + mt * 16 + (lane & 15);
        aH[mt] = s2u(&sAh[r * LDA + (lane >> 4) * 8]);
        aL[mt] = s2u(&sAl[r * LDA + (lane >> 4) * 8]);
    }
    unsigned bB = (lane < 16) ? s2u(&sWh[(lane & 15) * LDA + nw * 16])
                              : s2u(&sWl[(lane & 15) * LDA + nw * 16]);

#pragma unroll
    for (int ks = 0; ks < 8; ks++) {
        unsigned ah[2][4], al[2][4];
#pragma unroll
        for (int mt = 0; mt < 2; mt++) {
            LDSM_X4(ah[mt], aH[mt] + ks * 32);
            LDSM_X4(al[mt], aL[mt] + ks * 32);
        }
#pragma unroll
        for (int nt = 0; nt < 2; nt++) {
            unsigned b[4];                 // b[0..1]=Wh frag, b[2..3]=Wl frag
            LDSM_X4T(b, bB + ks * 16 * LDA * 2 + nt * 16);
#pragma unroll
            for (int mt = 0; mt < 2; mt++) {
                MMA16816(acc2[mt][nt], ah[mt], b[0], b[1]);
                MMA16816(acc2[mt][nt], ah[mt], b[2], b[3]);
                MMA16816(acc2[mt][nt], al[mt], b[0], b[1]);
            }
        }
    }

    // epilogue: layers 0-2 -> fp16 prescaled by src_norm; final -> fp32 ext
    __half* outh = (out_sel == 1) ? g_p0 : g_p1;
#pragma unroll
    for (int mt = 0; mt < 2; mt++) {
        int r0 = t * DD + mw * 32 + mt * 16 + (lane >> 2);
        int r1 = r0 + 8;
        float sn0 = 1.f, sn1 = 1.f;
        if (out_sel != 0) {
            if (r0 < NN) sn0 = __ldg(&g_src_norm[r0]);
            if (r1 < NN) sn1 = __ldg(&g_src_norm[r1]);
        }
#pragma unroll
        for (int nt = 0; nt < 2; nt++) {
            int col = nw * 16 + nt * 8 + (lane & 3) * 2;
            float2 bb = *(const float2*)&bias[col];
            if (out_sel == 0) {
                if (r0 < NN) {
                    float2 v; v.x = acc2[mt][nt][0] + bb.x; v.y = acc2[mt][nt][1] + bb.y;
                    *(float2*)&ext_out[(size_t)r0 * DD + col] = v;
                }
                if (r1 < NN) {
                    float2 v; v.x = acc2[mt][nt][2] + bb.x; v.y = acc2[mt][nt][3] + bb.y;
                    *(float2*)&ext_out[(size_t)r1 * DD + col] = v;
                }
            } else {
                if (r0 < NN) {
                    __half2 v = __floats2half2_rn((acc2[mt][nt][0] + bb.x) * sn0,
                                                  (acc2[mt][nt][1] + bb.y) * sn0);
                    *(__half2*)&outh[(size_t)r0 * DD + col] = v;
                }
                if (r1 < NN) {
                    __half2 v = __floats2half2_rn((acc2[mt][nt][2] + bb.x) * sn1,
                                                  (acc2[mt][nt][3] + bb.y) * sn1);
                    *(__half2*)&outh[(size_t)r1 * DD + col] = v;
                }
            }
        }
    }
}

// ---------------- launch ----------------
extern "C" void kernel_launch(void* const* d_in, const int* in_sizes, int n_in,
                              void* d_out, int out_size) {
    const float* feat = (const float*)d_in[0];
    const int*   src  = (const int*)d_in[1];
    const int*   dst  = (const int*)d_in[2];
    const float* W    = (const float*)d_in[3];
    const float* b    = (const float*)d_in[4];
    float* out = (float*)d_out;

    cudaFuncSetAttribute(k_fused, cudaFuncAttributeMaxDynamicSharedMemorySize, FSMEM);

    const int TB = 256;
    k_count<<<(NE + TB - 1) / TB, TB>>>(src, dst);         // 0
    k_bsum<<<NSB, 1024>>>();                               // 1
    k_finish<<<NSB, 1024>>>();                             // 2
    k_fill<<<(NE + TB - 1) / TB, TB>>>(src, dst);          // 3  <-- ncu-profiled slot
    k_wconv<<<(4 * DD * DD + TB - 1) / TB, TB>>>(W);       // 4
    k_prep<<<(NN * DD / 4 + TB - 1) / TB, TB>>>(feat);     // 5 (needs src_norm)

    k_fused<<<NT, 1024, FSMEM>>>(0, 0, b + 0 * DD, nullptr, 1);
    k_fused<<<NT, 1024, FSMEM>>>(1, 1, b + 1 * DD, nullptr, 2);
    k_fused<<<NT, 1024, FSMEM>>>(2, 2, b + 2 * DD, nullptr, 1);
    k_fused<<<NT, 1024, FSMEM>>>(1, 3, b + 3 * DD, out, 0);
}